// round 17
// baseline (speedup 1.0000x reference)
#include <cuda_runtime.h>
#include <cstdint>

#define D_DIM 128
#define MAX_N 200064
#define MAX_K 512

typedef unsigned int u32;
typedef unsigned long long u64;

__device__ float g_sums[MAX_K * D_DIM];
__device__ int   g_counts[MAX_K];
__device__ int   g_assign[MAX_N];
__device__ float g_c2[MAX_K];
__device__ float g_f2[MAX_N];
__device__ uint32_t g_Ctf[MAX_K * D_DIM];        // tf32 of centers

__device__ __forceinline__ uint32_t f2tf32(float x) {
    uint32_t r; asm("cvt.rna.tf32.f32 %0, %1;" : "=r"(r) : "f"(x)); return r;
}
__device__ __forceinline__ void mma_tf32(float* d, const uint32_t* a,
                                         uint32_t b0, uint32_t b1) {
    asm volatile(
        "mma.sync.aligned.m16n8k8.row.col.f32.tf32.tf32.f32 "
        "{%0,%1,%2,%3}, {%4,%5,%6,%7}, {%8,%9}, {%0,%1,%2,%3};"
        : "+f"(d[0]), "+f"(d[1]), "+f"(d[2]), "+f"(d[3])
        : "r"(a[0]), "r"(a[1]), "r"(a[2]), "r"(a[3]), "r"(b0), "r"(b1));
}
// monotonic float<->uint bijection (handles negatives)
__device__ __forceinline__ u32 fflip(float f) {
    u32 b = __float_as_uint(f);
    return b ^ (u32)(((int)b >> 31) | 0x80000000);
}
__device__ __forceinline__ float funflip(u32 u) {
    u32 m = ((int)u < 0) ? 0x80000000u : 0xFFFFFFFFu;
    return __uint_as_float(u ^ m);
}

// ---------------------------------------------------------------------------
// Fused prep: zero sums/counts, tf32-convert C, f2, c2.
// ---------------------------------------------------------------------------
__global__ void prep_kernel(const float* __restrict__ F,
                            const float* __restrict__ C, int N, int K) {
    const int t = blockIdx.x * blockDim.x + threadIdx.x;
    const int KD = K * D_DIM;
    if (t < KD) {
        g_sums[t] = 0.0f;
        g_Ctf[t] = f2tf32(C[t]);
    }
    if (t < K) g_counts[t] = 0;

    const int w = t >> 5;
    const int lane = t & 31;
    if (w < N) {
        float4 v = reinterpret_cast<const float4*>(F + (size_t)w * D_DIM)[lane];
        float s = v.x * v.x + v.y * v.y + v.z * v.z + v.w * v.w;
        #pragma unroll
        for (int o = 16; o > 0; o >>= 1) s += __shfl_xor_sync(0xffffffffu, s, o);
        if (lane == 0) g_f2[w] = s;
    } else if (w < N + K) {
        int k = w - N;
        float4 v = reinterpret_cast<const float4*>(C + (size_t)k * D_DIM)[lane];
        float s = v.x * v.x + v.y * v.y + v.z * v.z + v.w * v.w;
        #pragma unroll
        for (int o = 16; o > 0; o >>= 1) s += __shfl_xor_sync(0xffffffffu, s, o);
        if (lane == 0) g_c2[k] = s;
    }
}

// ---------------------------------------------------------------------------
// 1-pass tf32 mma + in-kernel candidate selection + exact fp32 rescore.
//   Block: 256 thr / 8 warps (4 M x 2 N). Tile: 128 points x 512 centers.
//   sA (64KB): F tile tf32, fragment-staged. sB (2x8KB): C chunk, dbl-buf.
//   Running per-point approx min (flipped u32, smem atomicMin); candidates
//   within EPS appended to smem list; exact fp32 rescore + packed u64
//   atomicMin argmin (score-major, lowest-k tie-break).
// ---------------------------------------------------------------------------
#define OFF_A   0
#define OFF_B   65536
#define OFF_TH  81920                 // 128 x u32
#define OFF_CNT 82432                 // 1 x int (padded)
#define OFF_RES 82944                 // 128 x u64
#define OFF_CND 83968                 // CAP x u32
#define CAP     4096
#define SMEM_TOTAL (OFF_CND + CAP * 4)
#define EPS 0.5f

__global__ __launch_bounds__(256, 2) void assign_kernel(
    const float* __restrict__ F, const float* __restrict__ Cf, int N, int K)
{
    extern __shared__ char smem[];
    uint32_t* sA  = reinterpret_cast<uint32_t*>(smem + OFF_A);
    uint32_t* sB  = reinterpret_cast<uint32_t*>(smem + OFF_B);
    u32*      sTh = reinterpret_cast<u32*>(smem + OFF_TH);
    int*      sCnt= reinterpret_cast<int*>(smem + OFF_CNT);
    u64*      sRes= reinterpret_cast<u64*>(smem + OFF_RES);
    u32*      sCnd= reinterpret_cast<u32*>(smem + OFF_CND);

    const int tid  = threadIdx.x;
    const int wid  = tid >> 5;
    const int lane = tid & 31;
    const int mw = wid & 3;
    const int nw = wid >> 2;
    const int g  = lane >> 2;
    const int q  = lane & 3;
    const int p0 = blockIdx.x * 128;

    if (tid < 128) { sTh[tid] = 0xFFFFFFFFu; sRes[tid] = 0xFFFFFFFFFFFFFFFFull; }
    if (tid == 0) *sCnt = 0;

    // ---- stage F tile into sA (tf32, fragment order; convert once) ----
    {
        int row = tid >> 1;
        int prow = p0 + row; if (prow >= N) prow = N - 1;
        const int dbase = (tid & 1) * 64;
        const float4* src = reinterpret_cast<const float4*>(
            F + (size_t)prow * D_DIM + dbase);
        const int mwmt = row >> 4;
        const int rbit = (row >> 3) & 1;
        const int lrow4 = (row & 7) * 4;
        #pragma unroll
        for (int j = 0; j < 16; ++j) {
            float4 v = src[j];
            float vv[4] = { v.x, v.y, v.z, v.w };
            #pragma unroll
            for (int e = 0; e < 4; ++e) {
                int d = dbase + j * 4 + e;
                int ks = d >> 3;
                int r  = ((d >> 2) & 1) * 2 + rbit;
                int ln = lrow4 + (d & 3);
                sA[((mwmt * 16 + ks) * 32 + ln) * 4 + r] = f2tf32(vv[e]);
            }
        }
    }

    float D[2][8][4];
    #pragma unroll
    for (int mt = 0; mt < 2; mt++)
        #pragma unroll
        for (int n = 0; n < 8; n++)
            #pragma unroll
            for (int e = 0; e < 4; e++) D[mt][n][e] = 0.0f;

    float f2v[4];
    #pragma unroll
    for (int s = 0; s < 4; s++) {
        int row = p0 + mw * 32 + (s >> 1) * 16 + g + 8 * (s & 1);
        if (row >= N) row = N - 1;
        f2v[s] = g_f2[row];
    }

    // ---- B loader (thread: center lc = tid>>1, 8 d's at ldh) ----
    const int lc   = tid >> 1;
    const int ldh  = (tid & 1) * 8;
    const int lg4  = (lc & 7) * 4;
    const int bslot = (lc >> 3) * 128;

    const int nkt = K >> 7;
    const int it_total = nkt * 8;

    uint4 h0, h1;
    {
        size_t base = (size_t)lc * D_DIM + ldh;
        h0 = *reinterpret_cast<const uint4*>(g_Ctf + base);
        h1 = *reinterpret_cast<const uint4*>(g_Ctf + base + 4);
    }
    {
        uint32_t* dst = sB;
        uint32_t hv[8] = { h0.x,h0.y,h0.z,h0.w, h1.x,h1.y,h1.z,h1.w };
        #pragma unroll
        for (int j = 0; j < 8; ++j) {
            int dd = ldh + j;
            dst[bslot + (lg4 + (dd & 3)) * 4 + (dd >> 3) * 2 + ((dd >> 2) & 1)] = hv[j];
        }
    }
    __syncthreads();

    for (int it = 0; it < it_total; ++it) {
        const int kt = it >> 3;
        const int dc = it & 7;
        const int cur = it & 1;
        const bool more = (it + 1 < it_total);

        if (more) {
            int nit = it + 1;
            size_t base = (size_t)(((nit >> 3) * 128) + lc) * D_DIM + (nit & 7) * 16 + ldh;
            h0 = *reinterpret_cast<const uint4*>(g_Ctf + base);
            h1 = *reinterpret_cast<const uint4*>(g_Ctf + base + 4);
        }

        // A fragments: 4 x LDS.128
        const int ks0 = dc * 2;
        uint4 ah[2][2];
        #pragma unroll
        for (int mt = 0; mt < 2; ++mt)
            #pragma unroll
            for (int kk = 0; kk < 2; ++kk)
                ah[mt][kk] = *reinterpret_cast<const uint4*>(
                    sA + (((mw * 2 + mt) * 16 + (ks0 + kk)) * 32 + lane) * 4);

        const uint32_t* bbuf = sB + cur * 2048;
        #pragma unroll
        for (int n = 0; n < 8; ++n) {
            uint4 bh = *reinterpret_cast<const uint4*>(
                bbuf + ((nw * 8 + n) * 32 + lane) * 4);
            #pragma unroll
            for (int mt = 0; mt < 2; ++mt) {
                mma_tf32(D[mt][n], reinterpret_cast<const uint32_t*>(&ah[mt][0]), bh.x, bh.y);
                mma_tf32(D[mt][n], reinterpret_cast<const uint32_t*>(&ah[mt][1]), bh.z, bh.w);
            }
        }

        if (more) {
            uint32_t* dst = sB + (cur ^ 1) * 2048;
            uint32_t hv[8] = { h0.x,h0.y,h0.z,h0.w, h1.x,h1.y,h1.z,h1.w };
            #pragma unroll
            for (int j = 0; j < 8; ++j) {
                int dd = ldh + j;
                dst[bslot + (lg4 + (dd & 3)) * 4 + (dd >> 3) * 2 + ((dd >> 2) & 1)] = hv[j];
            }
        }
        __syncthreads();

        // ---- k-tile boundary: scores -> running min -> candidate append ----
        if (dc == 7) {
            // part 1: convert D to scores in-place; update running per-row min
            float rmin[2][2] = { { __int_as_float(0x7f800000), __int_as_float(0x7f800000) },
                                 { __int_as_float(0x7f800000), __int_as_float(0x7f800000) } };
            #pragma unroll
            for (int n = 0; n < 8; ++n) {
                const int cb = kt * 128 + nw * 64 + n * 8 + 2 * q;
                const float c2a = g_c2[cb];
                const float c2b = g_c2[cb + 1];
                #pragma unroll
                for (int mt = 0; mt < 2; ++mt)
                    #pragma unroll
                    for (int h = 0; h < 2; ++h) {
                        const int s = mt * 2 + h;
                        float sa = (f2v[s] - 2.0f * D[mt][n][h * 2 + 0]) + c2a;
                        float sb = (f2v[s] - 2.0f * D[mt][n][h * 2 + 1]) + c2b;
                        D[mt][n][h * 2 + 0] = sa;
                        D[mt][n][h * 2 + 1] = sb;
                        rmin[mt][h] = fminf(rmin[mt][h], fminf(sa, sb));
                    }
            }
            #pragma unroll
            for (int mt = 0; mt < 2; ++mt)
                #pragma unroll
                for (int h = 0; h < 2; ++h) {
                    int row = mw * 32 + mt * 16 + g + 8 * h;
                    atomicMin(&sTh[row], fflip(rmin[mt][h]));
                }
            __syncthreads();
            // part 2: append candidates within EPS of running min; reset D
            float thv[2][2];
            #pragma unroll
            for (int mt = 0; mt < 2; ++mt)
                #pragma unroll
                for (int h = 0; h < 2; ++h) {
                    int row = mw * 32 + mt * 16 + g + 8 * h;
                    thv[mt][h] = funflip(sTh[row]) + EPS;
                }
            #pragma unroll
            for (int n = 0; n < 8; ++n) {
                const int cb = kt * 128 + nw * 64 + n * 8 + 2 * q;
                #pragma unroll
                for (int mt = 0; mt < 2; ++mt)
                    #pragma unroll
                    for (int h = 0; h < 2; ++h) {
                        const int row = mw * 32 + mt * 16 + g + 8 * h;
                        float sa = D[mt][n][h * 2 + 0];
                        float sb = D[mt][n][h * 2 + 1];
                        if (sa <= thv[mt][h]) {
                            int idx = atomicAdd(sCnt, 1);
                            if (idx < CAP) sCnd[idx] = ((u32)row << 9) | (u32)cb;
                        }
                        if (sb <= thv[mt][h]) {
                            int idx = atomicAdd(sCnt, 1);
                            if (idx < CAP) sCnd[idx] = ((u32)row << 9) | (u32)(cb + 1);
                        }
                        D[mt][n][h * 2 + 0] = 0.0f;
                        D[mt][n][h * 2 + 1] = 0.0f;
                    }
            }
            __syncthreads();
        }
    }

    // ---- exact fp32 rescore of candidates (sequential-d order) ----
    const int cnt = *sCnt;
    if (cnt <= CAP) {
        for (int c = tid; c < cnt; c += 256) {
            u32 u = sCnd[c];
            int row = (int)(u >> 9);
            int k   = (int)(u & 511u);
            int p = p0 + row; if (p >= N) p = N - 1;
            const float4* Fr = reinterpret_cast<const float4*>(F + (size_t)p * D_DIM);
            const float4* Cr = reinterpret_cast<const float4*>(Cf + (size_t)k * D_DIM);
            float dot = 0.0f;
            #pragma unroll
            for (int t = 0; t < 32; ++t) {
                float4 a = Fr[t];
                float4 b = Cr[t];
                dot = fmaf(a.x, b.x, dot);
                dot = fmaf(a.y, b.y, dot);
                dot = fmaf(a.z, b.z, dot);
                dot = fmaf(a.w, b.w, dot);
            }
            float sc = (g_f2[p] - 2.0f * dot) + g_c2[k];
            u64 pk = ((u64)fflip(sc) << 32) | (u64)(u32)k;
            atomicMin(&sRes[row], pk);
        }
    } else {
        // overflow fallback (never expected): rescore everything
        for (int c = tid; c < 128 * 512; c += 256) {
            int row = c >> 9;
            int k   = c & 511;
            int p = p0 + row; if (p >= N) p = N - 1;
            const float4* Fr = reinterpret_cast<const float4*>(F + (size_t)p * D_DIM);
            const float4* Cr = reinterpret_cast<const float4*>(Cf + (size_t)k * D_DIM);
            float dot = 0.0f;
            #pragma unroll
            for (int t = 0; t < 32; ++t) {
                float4 a = Fr[t];
                float4 b = Cr[t];
                dot = fmaf(a.x, b.x, dot);
                dot = fmaf(a.y, b.y, dot);
                dot = fmaf(a.z, b.z, dot);
                dot = fmaf(a.w, b.w, dot);
            }
            float sc = (g_f2[p] - 2.0f * dot) + g_c2[k];
            u64 pk = ((u64)fflip(sc) << 32) | (u64)(u32)k;
            atomicMin(&sRes[row], pk);
        }
    }
    __syncthreads();

    if (tid < 128 && p0 + tid < N)
        g_assign[p0 + tid] = (int)(sRes[tid] & 0xFFFFFFFFull);
}

// ---------------------------------------------------------------------------
// Segment sums: one warp per 4 points (MLP=4), v4 RED.
// ---------------------------------------------------------------------------
__global__ void seg_kernel(const float* __restrict__ F, int N) {
    int w = (blockIdx.x * blockDim.x + threadIdx.x) >> 5;
    int lane = threadIdx.x & 31;
    int pbase = w * 4;
    if (pbase >= N) return;
    float4 v[4]; int a[4]; bool ok[4];
    #pragma unroll
    for (int i = 0; i < 4; ++i) {
        int p = pbase + i;
        ok[i] = (p < N);
        int pc = ok[i] ? p : N - 1;
        a[i] = g_assign[pc];
        v[i] = reinterpret_cast<const float4*>(F + (size_t)pc * D_DIM)[lane];
    }
    #pragma unroll
    for (int i = 0; i < 4; ++i) {
        if (ok[i]) {
            float* dst = g_sums + (size_t)a[i] * D_DIM + lane * 4;
            asm volatile("red.global.add.v4.f32 [%0], {%1, %2, %3, %4};"
                         :: "l"(dst), "f"(v[i].x), "f"(v[i].y), "f"(v[i].z), "f"(v[i].w)
                         : "memory");
            if (lane == 0) atomicAdd(&g_counts[a[i]], 1);
        }
    }
}

__global__ void final_kernel(float* __restrict__ out, int KD, int nAssign) {
    int i = blockIdx.x * blockDim.x + threadIdx.x;
    if (i < KD) {
        float c = (float)g_counts[i / D_DIM];
        out[i] = g_sums[i] / fmaxf(c, 1.0f);
    } else {
        int a = i - KD;
        if (a < nAssign) out[KD + a] = (float)g_assign[a];
    }
}

// ---------------------------------------------------------------------------
extern "C" void kernel_launch(void* const* d_in, const int* in_sizes, int n_in,
                              void* d_out, int out_size)
{
    (void)n_in;
    const float* F = (const float*)d_in[0];
    const float* C = (const float*)d_in[1];
    const int D = D_DIM;
    const int N = in_sizes[0] / D;
    const int K = in_sizes[1] / D;
    float* out = (float*)d_out;
    const int KD = K * D;

    cudaFuncSetAttribute(assign_kernel,
                         cudaFuncAttributeMaxDynamicSharedMemorySize, SMEM_TOTAL);

    const int prepThreads = (N + K) * 32;
    prep_kernel<<<(prepThreads + 255) / 256, 256>>>(F, C, N, K);
    assign_kernel<<<(N + 127) / 128, 256, SMEM_TOTAL>>>(F, C, N, K);
    {
        int warps = (N + 3) / 4;
        int blocks = (warps * 32 + 255) / 256;
        seg_kernel<<<blocks, 256>>>(F, N);
    }

    int centersPart, assignPart;
    if (out_size >= KD + N)      { centersPart = KD; assignPart = N; }
    else if (out_size >= KD)     { centersPart = KD; assignPart = out_size - KD; }
    else                         { centersPart = 0;  assignPart = out_size; }
    int total = centersPart + assignPart;
    if (total > 0)
        final_kernel<<<(total + 255) / 256, 256>>>(out, centersPart, assignPart);
}